// round 11
// baseline (speedup 1.0000x reference)
#include <cuda_runtime.h>

// Problem constants
static constexpr int H    = 768;
static constexpr int B    = 64;
static constexpr int S1   = 513;
static constexpr int S    = 512;
static constexpr int NT   = 4;
static constexpr int NP   = 255;   // pair operators (steps 1..510)
static constexpr int NQ   = 127;   // quad operators (steps 1..508)
static constexpr int PSTR = 256;   // SoA stride for pair-level arrays
static constexpr int QSTR = 128;   // SoA stride for quad-level arrays
static constexpr int NROWS = B * S1;          // 32832
static constexpr int RPS   = 8;               // rows per stage
static constexpr int NSTG  = NROWS / RPS;     // 4104
static constexpr int STG_FLOATS = RPS * H;    // 6144 (24 KB)
static constexpr int STG_CHUNKS = STG_FLOATS / 4;  // 1536 x 16B
static constexpr int NBUF  = 3;
static constexpr int SMEM_BYTES = NBUF * STG_FLOATS * 4;  // 73728

// Output layout (flattened tuple, float32):
// [isqa_pred(64), crf_pred(64*512), isqa_loss(1), crf_loss(1), tags(64*512), IsQA(64)]
static constexpr int OFF_IPRED = 0;
static constexpr int OFF_CPRED = 64;
static constexpr int OFF_ILOSS = 64 + B * S;          // 32832
static constexpr int OFF_CLOSS = OFF_ILOSS + 1;       // 32833
static constexpr int OFF_TAGS  = OFF_CLOSS + 1;       // 32834
static constexpr int OFF_ISQA  = OFF_TAGS + B * S;    // 65602

__device__ __align__(16) float g_feats[B * S * NT];   // 512 KB
__device__ float g_logits[B * 2];
__device__ float g_dloss[B];
__device__ float g_iloss[B];

__device__ __forceinline__ int argmax4(float v0, float v1, float v2, float v3,
                                       float& mv) {
    // first-index tie-breaking (jnp.argmax): later wins only on strict >
    float mA = fmaxf(v0, v1); int iA = (v1 > v0) ? 1 : 0;
    float mB = fmaxf(v2, v3); int iB = (v3 > v2) ? 3 : 2;
    mv = fmaxf(mA, mB);
    return (mB > mA) ? iB : iA;
}

__device__ __forceinline__ void mm4(const float* A, const float* Bm, float* C) {
#pragma unroll
    for (int i = 0; i < 4; i++)
#pragma unroll
        for (int j = 0; j < 4; j++)
            C[i * 4 + j] = (A[i * 4 + 0] * Bm[0 * 4 + j] + A[i * 4 + 1] * Bm[1 * 4 + j]) +
                           (A[i * 4 + 2] * Bm[2 * 4 + j] + A[i * 4 + 3] * Bm[3 * 4 + j]);
}

__device__ __forceinline__ void mp4(const float* A, const float* Bm, float* C) {
#pragma unroll
    for (int i = 0; i < 4; i++)
#pragma unroll
        for (int j = 0; j < 4; j++)
            C[i * 4 + j] = fmaxf(fmaxf(A[i * 4 + 0] + Bm[0 * 4 + j],
                                       A[i * 4 + 1] + Bm[1 * 4 + j]),
                                 fmaxf(A[i * 4 + 2] + Bm[2 * 4 + j],
                                       A[i * 4 + 3] + Bm[3 * 4 + j]));
}

// ---------------------------------------------------------------------------
// Kernel 1: emission features + isqa logits.
// cp.async 3-stage ring of 24KB stages (dynamic smem, 72KB), crf_W in
// registers, 2 rows per warp per stage (weight-register reuse, double ILP,
// half the barrier events of the 12KB-stage version).
// ---------------------------------------------------------------------------
__global__ void __launch_bounds__(128, 3)
k_feats(const float* __restrict__ emb,
        const float* __restrict__ fc2_W,
        const float* __restrict__ fc2_b,
        const float* __restrict__ crf_W,
        const float* __restrict__ crf_b) {
    extern __shared__ __align__(16) float sbuf[];   // NBUF * STG_FLOATS

    const int tid  = threadIdx.x;
    const int lane = tid & 31;
    const int w    = tid >> 5;          // warp id (0..3)
    const int G    = gridDim.x;

    // Weights in registers: lane's column slice
    float4 wr[NT][6];
#pragma unroll
    for (int t = 0; t < NT; t++)
#pragma unroll
        for (int k = 0; k < 6; k++)
            wr[t][k] = __ldg(reinterpret_cast<const float4*>(crf_W + t * H) + k * 32 + lane);
    const float cb0 = __ldg(crf_b + 0), cb1 = __ldg(crf_b + 1);
    const float cb2 = __ldg(crf_b + 2), cb3 = __ldg(crf_b + 3);

#define ISSUE_STAGE(gidx, bidx)                                                        \
    do {                                                                               \
        const float* _src = emb + (size_t)(gidx) * STG_FLOATS;                         \
        float* _dst = sbuf + (bidx) * STG_FLOATS;                                      \
        _Pragma("unroll")                                                              \
        for (int c = tid; c < STG_CHUNKS; c += 128) {                                  \
            unsigned _sa = (unsigned)__cvta_generic_to_shared(_dst + c * 4);           \
            asm volatile("cp.async.cg.shared.global [%0], [%1], 16;\n"                 \
                         :: "r"(_sa), "l"(_src + c * 4));                              \
        }                                                                              \
        asm volatile("cp.async.commit_group;\n");                                      \
    } while (0)

    const int g0 = blockIdx.x;
    if (g0 < NSTG)     ISSUE_STAGE(g0, 0);
    if (g0 + G < NSTG) ISSUE_STAGE(g0 + G, 1);

    int buf = 0;
    for (int g = g0; g < NSTG; g += G) {
        const int gn = g + 2 * G;
        if (gn < NSTG) {
            ISSUE_STAGE(gn, (buf + 2) % NBUF);
            asm volatile("cp.async.wait_group 2;\n");
        } else if (g + G < NSTG) {
            asm volatile("cp.async.wait_group 1;\n");
        } else {
            asm volatile("cp.async.wait_group 0;\n");
        }
        __syncthreads();

        // ---- warp w computes rows r0, r0+1 of this stage ----
        const int r0 = g * RPS + 2 * w;
        const int b0 = r0 / S1;
        const int s0 = r0 - b0 * S1;
        const int r1 = r0 + 1;
        const int b1 = r1 / S1;
        const int s1 = r1 - b1 * S1;
        const float* base = sbuf + buf * STG_FLOATS;
        const float4* e0 = reinterpret_cast<const float4*>(base + (2 * w) * H);
        const float4* e1 = reinterpret_cast<const float4*>(base + (2 * w + 1) * H);

        if (s0 != 0 && s1 != 0) {
            // fast fused path (both CRF rows)
            float a0[NT] = {0.f, 0.f, 0.f, 0.f};
            float a1[NT] = {0.f, 0.f, 0.f, 0.f};
#pragma unroll
            for (int k = 0; k < 6; k++) {
                float4 x0 = e0[k * 32 + lane];
                float4 x1 = e1[k * 32 + lane];
#pragma unroll
                for (int t = 0; t < NT; t++) {
                    a0[t] += x0.x * wr[t][k].x + x0.y * wr[t][k].y +
                             x0.z * wr[t][k].z + x0.w * wr[t][k].w;
                    a1[t] += x1.x * wr[t][k].x + x1.y * wr[t][k].y +
                             x1.z * wr[t][k].z + x1.w * wr[t][k].w;
                }
            }
#pragma unroll
            for (int off = 16; off; off >>= 1)
#pragma unroll
                for (int t = 0; t < NT; t++) {
                    a0[t] += __shfl_xor_sync(0xFFFFFFFFu, a0[t], off);
                    a1[t] += __shfl_xor_sync(0xFFFFFFFFu, a1[t], off);
                }
            if (lane == 0) {
                reinterpret_cast<float4*>(g_feats)[b0 * S + (s0 - 1)] =
                    make_float4(a0[0] + cb0, a0[1] + cb1, a0[2] + cb2, a0[3] + cb3);
                reinterpret_cast<float4*>(g_feats)[b1 * S + (s1 - 1)] =
                    make_float4(a1[0] + cb0, a1[1] + cb1, a1[2] + cb2, a1[3] + cb3);
            }
        } else {
            // slow path: at least one cls row (64 of 32832 rows hit this)
#pragma unroll
            for (int rr = 0; rr < 2; rr++) {
                const int bb = rr ? b1 : b0;
                const int ss = rr ? s1 : s0;
                const float4* e = rr ? e1 : e0;
                if (ss == 0) {
                    float l0 = 0.f, l1 = 0.f;
#pragma unroll
                    for (int k = 0; k < 6; k++) {
                        float4 x  = e[k * 32 + lane];
                        float4 w0 = __ldg(reinterpret_cast<const float4*>(fc2_W) + k * 32 + lane);
                        float4 w1 = __ldg(reinterpret_cast<const float4*>(fc2_W + H) + k * 32 + lane);
                        l0 += x.x * w0.x + x.y * w0.y + x.z * w0.z + x.w * w0.w;
                        l1 += x.x * w1.x + x.y * w1.y + x.z * w1.z + x.w * w1.w;
                    }
#pragma unroll
                    for (int off = 16; off; off >>= 1) {
                        l0 += __shfl_xor_sync(0xFFFFFFFFu, l0, off);
                        l1 += __shfl_xor_sync(0xFFFFFFFFu, l1, off);
                    }
                    if (lane == 0) {
                        g_logits[bb * 2 + 0] = l0 + __ldg(fc2_b + 0);
                        g_logits[bb * 2 + 1] = l1 + __ldg(fc2_b + 1);
                    }
                } else {
                    float acc[NT] = {0.f, 0.f, 0.f, 0.f};
#pragma unroll
                    for (int k = 0; k < 6; k++) {
                        float4 x = e[k * 32 + lane];
#pragma unroll
                        for (int t = 0; t < NT; t++)
                            acc[t] += x.x * wr[t][k].x + x.y * wr[t][k].y +
                                      x.z * wr[t][k].z + x.w * wr[t][k].w;
                    }
#pragma unroll
                    for (int off = 16; off; off >>= 1)
#pragma unroll
                        for (int t = 0; t < NT; t++)
                            acc[t] += __shfl_xor_sync(0xFFFFFFFFu, acc[t], off);
                    if (lane == 0) {
                        reinterpret_cast<float4*>(g_feats)[bb * S + (ss - 1)] =
                            make_float4(acc[0] + cb0, acc[1] + cb1,
                                        acc[2] + cb2, acc[3] + cb3);
                    }
                }
            }
        }
        __syncthreads();
        buf = (buf + 1) % NBUF;
    }
#undef ISSUE_STAGE
}

// ---------------------------------------------------------------------------
// Kernel 2: per-batch CRF, SoA operator storage (conflict-free LDS).
//  Forward Z : binary tree over 255 M2 matrices (normalized + log accum)
//  Viterbi   : Hillis-Steele max-plus scan over 127 V4 ops, parallel
//              backtrace records, 127-step serial record chase.
// ---------------------------------------------------------------------------
__global__ void __launch_bounds__(256) k_crf(const int* __restrict__ labels,
                                             const int* __restrict__ isqa,
                                             const float* __restrict__ trans,
                                             float* __restrict__ out) {
    __shared__ __align__(16) float sf[S * NT];     // 8 KB feats (log)
    __shared__ float sA[16 * PSTR];                // 16 KB: M2 then V2 (SoA)
    __shared__ float sV4[16 * QSTR];               // 8 KB (SoA)
    __shared__ float sPa[16 * QSTR];               // 8 KB tree/scan buffer (SoA)
    __shared__ float slogs[QSTR];
    __shared__ float strn[16], sE[16];
    __shared__ int   sbpmid2[PSTR];
    __shared__ int   skmid4[QSTR];
    __shared__ unsigned int srec[QSTR];
    __shared__ unsigned char stag[S], spath[S];
    __shared__ float sZ;

    const int b   = blockIdx.x;
    const int tid = threadIdx.x;
    const float4* sf4 = reinterpret_cast<const float4*>(sf);

    // ---- P0: stage ----
    {
        const float4* fsrc = reinterpret_cast<const float4*>(g_feats + (size_t)b * S * NT);
        float4* f4 = reinterpret_cast<float4*>(sf);
        for (int i = tid; i < S; i += 256) f4[i] = fsrc[i];
        for (int i = tid; i < S; i += 256) {
            int tg = labels[b * S1 + 1 + i];
            stag[i] = (unsigned char)tg;
            out[OFF_TAGS + b * S + i] = (float)tg;
        }
        if (tid < 16) { float t = trans[tid]; strn[tid] = t; sE[tid] = __expf(t); }
    }
    __syncthreads();

    // ---- P1: M2 pair matrices (linear domain), one per thread, SoA store ----
    if (tid < NP) {
        const int p = tid;
        float4 f1 = sf4[2 * p + 1], f2 = sf4[2 * p + 2];
        float g[4] = {__expf(f1.x), __expf(f1.y), __expf(f1.z), __expf(f1.w)};
        float h[4] = {__expf(f2.x), __expf(f2.y), __expf(f2.z), __expf(f2.w)};
        float m[16];
#pragma unroll
        for (int i = 0; i < 4; i++) {
            float eg0 = sE[i * 4 + 0] * g[0], eg1 = sE[i * 4 + 1] * g[1];
            float eg2 = sE[i * 4 + 2] * g[2], eg3 = sE[i * 4 + 3] * g[3];
#pragma unroll
            for (int j = 0; j < 4; j++)
                m[i * 4 + j] = ((eg0 * sE[0 * 4 + j] + eg1 * sE[1 * 4 + j]) +
                                (eg2 * sE[2 * 4 + j] + eg3 * sE[3 * 4 + j])) * h[j];
        }
#pragma unroll
        for (int e = 0; e < 16; e++) sA[e * PSTR + p] = m[e];
    }
    __syncthreads();

    // ---- P2: forward Z via tree reduction over sPa (SoA) ----
    if (tid < 128) {
        float C[16];
        if (tid < 127) {
            float A[16], Bm[16];
#pragma unroll
            for (int e = 0; e < 16; e++) { A[e] = sA[e * PSTR + 2 * tid];
                                           Bm[e] = sA[e * PSTR + 2 * tid + 1]; }
            mm4(A, Bm, C);
        } else {
#pragma unroll
            for (int e = 0; e < 16; e++) C[e] = sA[e * PSTR + 254];
        }
        float ssum = 0.f;
#pragma unroll
        for (int e = 0; e < 16; e++) ssum += C[e];
        float inv = __fdividef(1.0f, ssum);
#pragma unroll
        for (int e = 0; e < 16; e++) sPa[e * QSTR + tid] = C[e] * inv;
        slogs[tid] = __logf(ssum);
    }
    __syncthreads();
#pragma unroll
    for (int n = 64; n >= 1; n >>= 1) {
        float C[16], lg = 0.f;
        if (tid < n) {
            float A[16], Bm[16];
#pragma unroll
            for (int e = 0; e < 16; e++) { A[e] = sPa[e * QSTR + 2 * tid];
                                           Bm[e] = sPa[e * QSTR + 2 * tid + 1]; }
            mm4(A, Bm, C);
            lg = slogs[2 * tid] + slogs[2 * tid + 1];
        }
        __syncthreads();
        if (tid < n) {
            float ssum = 0.f;
#pragma unroll
            for (int e = 0; e < 16; e++) ssum += C[e];
            float inv = __fdividef(1.0f, ssum);
#pragma unroll
            for (int e = 0; e < 16; e++) sPa[e * QSTR + tid] = C[e] * inv;
            slogs[tid] = lg + __logf(ssum);
        }
        __syncthreads();
    }
    if (tid == 0) {   // Z epilogue: alpha0 . Mtot, then step 511 + stop
        float4 f0 = sf4[0];
        float a[4] = {__expf(f0.x) * sE[8],  __expf(f0.y) * sE[9],
                      __expf(f0.z) * sE[10], __expf(f0.w) * sE[11]};
        float Mt[16];
#pragma unroll
        for (int e = 0; e < 16; e++) Mt[e] = sPa[e * QSTR + 0];
        float t[4];
#pragma unroll
        for (int j = 0; j < 4; j++)
            t[j] = (a[0] * Mt[0 * 4 + j] + a[1] * Mt[1 * 4 + j]) +
                   (a[2] * Mt[2 * 4 + j] + a[3] * Mt[3 * 4 + j]);
        float4 f511 = sf4[511];
        float ef[4] = {__expf(f511.x), __expf(f511.y), __expf(f511.z), __expf(f511.w)};
        float u[4];
#pragma unroll
        for (int j = 0; j < 4; j++)
            u[j] = ((t[0] * sE[0 * 4 + j] + t[1] * sE[1 * 4 + j]) +
                    (t[2] * sE[2 * 4 + j] + t[3] * sE[3 * 4 + j])) * ef[j];
        sZ = slogs[0] + __logf((u[0] * sE[3] + u[1] * sE[7]) +
                               (u[2] * sE[11] + u[3] * sE[15]));
    }
    __syncthreads();

    // ---- P3: V2 (max-plus) overwrites sA (SoA); mid-tag words ----
    if (tid < NP) {
        const int p = tid;
        float4 f1 = sf4[2 * p + 1], f2 = sf4[2 * p + 2];
        float f1a[4] = {f1.x, f1.y, f1.z, f1.w};
        float f2a[4] = {f2.x, f2.y, f2.z, f2.w};
        int word = 0;
#pragma unroll
        for (int i = 0; i < 4; i++) {
            float h0 = strn[i * 4 + 0] + f1a[0], h1 = strn[i * 4 + 1] + f1a[1];
            float h2 = strn[i * 4 + 2] + f1a[2], h3 = strn[i * 4 + 3] + f1a[3];
#pragma unroll
            for (int j = 0; j < 4; j++) {
                float mv;
                int k = argmax4(h0 + strn[0 * 4 + j], h1 + strn[1 * 4 + j],
                                h2 + strn[2 * 4 + j], h3 + strn[3 * 4 + j], mv);
                sA[(i * 4 + j) * PSTR + p] = mv + f2a[j];
                word |= k << (2 * (i * 4 + j));
            }
        }
        sbpmid2[p] = word;
    }
    __syncthreads();

    // ---- P4: V4 = V2 o V2 into sV4 and sPa (scan init); mid words ----
    if (tid < NQ) {
        float A[16], Bv[16];
#pragma unroll
        for (int e = 0; e < 16; e++) { A[e] = sA[e * PSTR + 2 * tid];
                                       Bv[e] = sA[e * PSTR + 2 * tid + 1]; }
        int word = 0;
#pragma unroll
        for (int i = 0; i < 4; i++)
#pragma unroll
            for (int j = 0; j < 4; j++) {
                float mv;
                int k = argmax4(A[i * 4 + 0] + Bv[0 * 4 + j], A[i * 4 + 1] + Bv[1 * 4 + j],
                                A[i * 4 + 2] + Bv[2 * 4 + j], A[i * 4 + 3] + Bv[3 * 4 + j], mv);
                sV4[(i * 4 + j) * QSTR + tid] = mv;
                sPa[(i * 4 + j) * QSTR + tid] = mv;
                word |= k << (2 * (i * 4 + j));
            }
        skmid4[tid] = word;
    }
    __syncthreads();

    // ---- P5: inclusive max-plus scan (Hillis-Steele, SoA) ----
#pragma unroll
    for (int d = 1; d < 128; d <<= 1) {
        float C[16];
        const bool act = (tid < NQ) && (tid >= d);
        if (act) {
            float A[16], Bm[16];
#pragma unroll
            for (int e = 0; e < 16; e++) { A[e] = sPa[e * QSTR + tid - d];
                                           Bm[e] = sPa[e * QSTR + tid]; }
            mp4(A, Bm, C);
        }
        __syncthreads();
        if (act) {
#pragma unroll
            for (int e = 0; e < 16; e++) sPa[e * QSTR + tid] = C[e];
        }
        __syncthreads();
    }

    // ---- P6: per-quad backtrace records (parallel) ----
    if (tid < NQ) {
        const int q = tid;
        float4 f0 = sf4[0];
        float d0v[4] = {f0.x + strn[8], f0.y + strn[9], f0.z + strn[10], f0.w + strn[11]};
        float de[4];
        if (q == 0) {
#pragma unroll
            for (int i = 0; i < 4; i++) de[i] = d0v[i];
        } else {
            float P[16];
#pragma unroll
            for (int e = 0; e < 16; e++) P[e] = sPa[e * QSTR + q - 1];
#pragma unroll
            for (int j = 0; j < 4; j++) {
                float mv;
                argmax4(d0v[0] + P[0 * 4 + j], d0v[1] + P[1 * 4 + j],
                        d0v[2] + P[2 * 4 + j], d0v[3] + P[3 * 4 + j], mv);
                de[j] = mv;
            }
        }
        float V[16];
#pragma unroll
        for (int e = 0; e < 16; e++) V[e] = sV4[e * QSTR + q];
        const int w4 = skmid4[q], w2a = sbpmid2[2 * q], w2b = sbpmid2[2 * q + 1];
        unsigned int rec = 0;
#pragma unroll
        for (int j = 0; j < 4; j++) {
            float mv;
            int i = argmax4(de[0] + V[0 * 4 + j], de[1] + V[1 * 4 + j],
                            de[2] + V[2 * 4 + j], de[3] + V[3 * 4 + j], mv);
            int k2 = (w4  >> (2 * ((i  << 2) | j)))  & 3;
            int m1 = (w2a >> (2 * ((i  << 2) | k2))) & 3;
            int m3 = (w2b >> (2 * ((k2 << 2) | j)))  & 3;
            rec |= (unsigned int)(i | (m1 << 2) | (k2 << 4) | (m3 << 6)) << (8 * j);
        }
        srec[q] = rec;
    }
    __syncthreads();

    // ---- P7: viterbi epilogue + serial record chase (tid 0) ----
    if (tid == 0) {
        float4 f0 = sf4[0];
        float d0v[4] = {f0.x + strn[8], f0.y + strn[9], f0.z + strn[10], f0.w + strn[11]};
        float P[16];
#pragma unroll
        for (int e = 0; e < 16; e++) P[e] = sPa[e * QSTR + 126];
        float e[4];
#pragma unroll
        for (int j = 0; j < 4; j++) {
            float mv;
            argmax4(d0v[0] + P[0 * 4 + j], d0v[1] + P[1 * 4 + j],
                    d0v[2] + P[2 * 4 + j], d0v[3] + P[3 * 4 + j], mv);
            e[j] = mv;
        }
        float Vl[16];
#pragma unroll
        for (int k = 0; k < 16; k++) Vl[k] = sA[k * PSTR + 254];
        float g0 = fmaxf(fmaxf(e[0] + Vl[0], e[1] + Vl[4]), fmaxf(e[2] + Vl[8],  e[3] + Vl[12]));
        float g1 = fmaxf(fmaxf(e[0] + Vl[1], e[1] + Vl[5]), fmaxf(e[2] + Vl[9],  e[3] + Vl[13]));
        float g2 = fmaxf(fmaxf(e[0] + Vl[2], e[1] + Vl[6]), fmaxf(e[2] + Vl[10], e[3] + Vl[14]));
        float g3 = fmaxf(fmaxf(e[0] + Vl[3], e[1] + Vl[7]), fmaxf(e[2] + Vl[11], e[3] + Vl[15]));
        float4 f511 = sf4[511];
        float h0 = fmaxf(fmaxf(g0 + strn[0], g1 + strn[4]), fmaxf(g2 + strn[8],  g3 + strn[12])) + f511.x;
        float h1 = fmaxf(fmaxf(g0 + strn[1], g1 + strn[5]), fmaxf(g2 + strn[9],  g3 + strn[13])) + f511.y;
        float h2 = fmaxf(fmaxf(g0 + strn[2], g1 + strn[6]), fmaxf(g2 + strn[10], g3 + strn[14])) + f511.z;
        float h3 = fmaxf(fmaxf(g0 + strn[3], g1 + strn[7]), fmaxf(g2 + strn[11], g3 + strn[15])) + f511.w;
        float mv;
        int lt = argmax4(h0 + strn[3], h1 + strn[7], h2 + strn[11], h3 + strn[15], mv);
        spath[511] = (unsigned char)lt;
        int t510 = argmax4(g0 + strn[0 * 4 + lt], g1 + strn[1 * 4 + lt],
                           g2 + strn[2 * 4 + lt], g3 + strn[3 * 4 + lt], mv);
        spath[510] = (unsigned char)t510;
        int j = t510;
        int i508 = argmax4(e[0] + Vl[0 * 4 + j], e[1] + Vl[1 * 4 + j],
                           e[2] + Vl[2 * 4 + j], e[3] + Vl[3 * 4 + j], mv);
        int mid = (sbpmid2[254] >> (2 * ((i508 << 2) | j))) & 3;
        spath[509] = (unsigned char)mid;
        spath[508] = (unsigned char)i508;
        j = i508;
        unsigned int* path32 = reinterpret_cast<unsigned int*>(spath);
#pragma unroll 4
        for (int q = NQ - 1; q >= 0; q--) {
            unsigned int w = srec[q];
            unsigned int r = (w >> (8 * j)) & 255u;
            path32[q] = (r & 3u) | (((r >> 2) & 3u) << 8) |
                        (((r >> 4) & 3u) << 16) | (((r >> 6) & 3u) << 24);
            j = (int)(r & 3u);
        }
    }
    __syncthreads();

    // ---- P8: gold score (warp 0), isqa (tid 32), path writeback (all) ----
    const int warp = tid >> 5, lane = tid & 31;
    if (warp == 0) {
        float em = 0.f, tr = 0.f;
        for (int s = lane; s < S; s += 32)     em += sf[s * NT + stag[s]];
        for (int s = lane; s < S - 1; s += 32) tr += strn[stag[s] * NT + stag[s + 1]];
        float v = em + tr;
#pragma unroll
        for (int off = 16; off; off >>= 1) v += __shfl_xor_sync(0xFFFFFFFFu, v, off);
        if (lane == 0) {
            float gold = v + strn[8 + stag[0]] + strn[stag[S - 1] * 4 + 3];
            g_dloss[b] = sZ - gold;
        }
    } else if (tid == 32) {
        float l0 = g_logits[b * 2], l1 = g_logits[b * 2 + 1];
        float mm  = fmaxf(l0, l1);
        float lse = mm + __logf(__expf(l0 - mm) + __expf(l1 - mm));
        int y = isqa[b];
        g_iloss[b] = -((y ? l1 : l0) - lse);
        out[OFF_IPRED + b] = (l1 > l0) ? 1.0f : 0.0f;
        out[OFF_ISQA + b] = (float)y;
    }
    for (int i = tid; i < S; i += 256)
        out[OFF_CPRED + b * S + i] = (float)spath[i];
}

// ---------------------------------------------------------------------------
// Kernel 3: reduce per-batch losses
// ---------------------------------------------------------------------------
__global__ void k_final(float* __restrict__ out) {
    const int tid = threadIdx.x;   // 64 threads
    float d  = g_dloss[tid];
    float il = g_iloss[tid];
#pragma unroll
    for (int off = 16; off; off >>= 1) {
        d  += __shfl_xor_sync(0xFFFFFFFFu, d, off);
        il += __shfl_xor_sync(0xFFFFFFFFu, il, off);
    }
    __shared__ float sd2[2], si2[2];
    if ((tid & 31) == 0) { sd2[tid >> 5] = d; si2[tid >> 5] = il; }
    __syncthreads();
    if (tid == 0) {
        out[OFF_CLOSS] = (sd2[0] + sd2[1]) * (1.0f / 64.0f);
        out[OFF_ILOSS] = (si2[0] + si2[1]) * (1.0f / 64.0f);
    }
}

// ---------------------------------------------------------------------------
extern "C" void kernel_launch(void* const* d_in, const int* in_sizes, int n_in,
                              void* d_out, int out_size) {
    const float* emb    = (const float*)d_in[0];
    const int*   labels = (const int*)d_in[1];
    const int*   isqa   = (const int*)d_in[2];
    const float* fc2_W  = (const float*)d_in[3];
    const float* fc2_b  = (const float*)d_in[4];
    const float* crf_W  = (const float*)d_in[5];
    const float* crf_b  = (const float*)d_in[6];
    const float* trans  = (const float*)d_in[7];
    float* out = (float*)d_out;

    cudaFuncSetAttribute(k_feats, cudaFuncAttributeMaxDynamicSharedMemorySize,
                         SMEM_BYTES);
    k_feats<<<444, 128, SMEM_BYTES>>>(emb, fc2_W, fc2_b, crf_W, crf_b);
    k_crf<<<B, 256>>>(labels, isqa, trans, out);
    k_final<<<1, 64>>>(out);
}

// round 12
// speedup vs baseline: 1.4012x; 1.4012x over previous
#include <cuda_runtime.h>

// Problem constants
static constexpr int H    = 768;
static constexpr int B    = 64;
static constexpr int S1   = 513;
static constexpr int S    = 512;
static constexpr int NT   = 4;
static constexpr int NP   = 255;   // pair operators (steps 1..510)
static constexpr int NQ   = 127;   // quad operators (steps 1..508)
static constexpr int PSTR = 256;   // SoA stride for pair-level arrays
static constexpr int QSTR = 128;   // SoA stride for quad-level arrays
static constexpr int NROWS  = B * S1;        // 32832
static constexpr int NITEMS = NROWS / 2;     // 16416 (2 rows per item)
static constexpr int STG_FLOATS = 2 * H;     // 1536 floats = 6 KB per stage
static constexpr int STG_CHUNKS = STG_FLOATS / 4;  // 384 x 16B
static constexpr int NBUF = 3;               // per-warp ring depth
static constexpr int WARPS_PER_BLK = 4;
static constexpr int SMEM_BYTES = WARPS_PER_BLK * NBUF * STG_FLOATS * 4;  // 73728

// Output layout (flattened tuple, float32):
// [isqa_pred(64), crf_pred(64*512), isqa_loss(1), crf_loss(1), tags(64*512), IsQA(64)]
static constexpr int OFF_IPRED = 0;
static constexpr int OFF_CPRED = 64;
static constexpr int OFF_ILOSS = 64 + B * S;          // 32832
static constexpr int OFF_CLOSS = OFF_ILOSS + 1;       // 32833
static constexpr int OFF_TAGS  = OFF_CLOSS + 1;       // 32834
static constexpr int OFF_ISQA  = OFF_TAGS + B * S;    // 65602

__device__ __align__(16) float g_feats[B * S * NT];   // 512 KB
__device__ float g_logits[B * 2];
__device__ float g_dloss[B];
__device__ float g_iloss[B];

__device__ __forceinline__ int argmax4(float v0, float v1, float v2, float v3,
                                       float& mv) {
    // first-index tie-breaking (jnp.argmax): later wins only on strict >
    float mA = fmaxf(v0, v1); int iA = (v1 > v0) ? 1 : 0;
    float mB = fmaxf(v2, v3); int iB = (v3 > v2) ? 3 : 2;
    mv = fmaxf(mA, mB);
    return (mB > mA) ? iB : iA;
}

__device__ __forceinline__ void mm4(const float* A, const float* Bm, float* C) {
#pragma unroll
    for (int i = 0; i < 4; i++)
#pragma unroll
        for (int j = 0; j < 4; j++)
            C[i * 4 + j] = (A[i * 4 + 0] * Bm[0 * 4 + j] + A[i * 4 + 1] * Bm[1 * 4 + j]) +
                           (A[i * 4 + 2] * Bm[2 * 4 + j] + A[i * 4 + 3] * Bm[3 * 4 + j]);
}

__device__ __forceinline__ void mp4(const float* A, const float* Bm, float* C) {
#pragma unroll
    for (int i = 0; i < 4; i++)
#pragma unroll
        for (int j = 0; j < 4; j++)
            C[i * 4 + j] = fmaxf(fmaxf(A[i * 4 + 0] + Bm[0 * 4 + j],
                                       A[i * 4 + 1] + Bm[1 * 4 + j]),
                                 fmaxf(A[i * 4 + 2] + Bm[2 * 4 + j],
                                       A[i * 4 + 3] + Bm[3 * 4 + j]));
}

// ---------------------------------------------------------------------------
// Kernel 1: emission features + isqa logits.
// PER-WARP cp.async pipeline: each warp owns a private 3x6KB smem ring and
// waits only on its own groups (uniform commit -> wait_group 2 always valid,
// __syncwarp only, NO block barriers). 12 warps/SM x 12KB in flight = 144KB/SM.
// Weights in registers; 2 rows per item.
// ---------------------------------------------------------------------------
__global__ void __launch_bounds__(128, 3)
k_feats(const float* __restrict__ emb,
        const float* __restrict__ fc2_W,
        const float* __restrict__ fc2_b,
        const float* __restrict__ crf_W,
        const float* __restrict__ crf_b) {
    extern __shared__ __align__(16) float sbuf[];   // WARPS_PER_BLK*NBUF*STG_FLOATS

    const int tid  = threadIdx.x;
    const int lane = tid & 31;
    const int w    = tid >> 5;
    const int NW   = gridDim.x * WARPS_PER_BLK;       // total warps
    const int gw   = blockIdx.x * WARPS_PER_BLK + w;  // this warp's id
    float* ring = sbuf + w * NBUF * STG_FLOATS;

    // Weights in registers: lane's column slice
    float4 wr[NT][6];
#pragma unroll
    for (int t = 0; t < NT; t++)
#pragma unroll
        for (int k = 0; k < 6; k++)
            wr[t][k] = __ldg(reinterpret_cast<const float4*>(crf_W + t * H) + k * 32 + lane);
    const float cb0 = __ldg(crf_b + 0), cb1 = __ldg(crf_b + 1);
    const float cb2 = __ldg(crf_b + 2), cb3 = __ldg(crf_b + 3);

    // Issue one 2-row stage (lane-strided 16B chunks), ALWAYS commit
    // (empty group when out of range keeps group counting uniform).
#define ISSUE_STAGE(itemIdx, dstPtr)                                                   \
    do {                                                                               \
        if ((itemIdx) < NITEMS) {                                                      \
            const float* _src = emb + (size_t)(itemIdx) * STG_FLOATS;                  \
            float* _dst = (dstPtr);                                                    \
            _Pragma("unroll")                                                          \
            for (int c = lane; c < STG_CHUNKS; c += 32) {                              \
                unsigned _sa = (unsigned)__cvta_generic_to_shared(_dst + c * 4);       \
                asm volatile("cp.async.cg.shared.global [%0], [%1], 16;\n"             \
                             :: "r"(_sa), "l"(_src + c * 4));                          \
            }                                                                          \
        }                                                                              \
        asm volatile("cp.async.commit_group;\n");                                      \
    } while (0)

    // Prologue: fill the ring
#pragma unroll
    for (int p = 0; p < NBUF; p++)
        ISSUE_STAGE(gw + p * NW, ring + p * STG_FLOATS);

    int buf = 0;
    for (int it = gw; it < NITEMS; it += NW) {
        // Oldest outstanding group is this iteration's stage.
        asm volatile("cp.async.wait_group %0;\n" :: "n"(NBUF - 1));
        __syncwarp();

        const int r0 = 2 * it;
        const int b0 = r0 / S1;
        const int s0 = r0 - b0 * S1;
        const int r1 = r0 + 1;
        const int b1 = r1 / S1;
        const int s1 = r1 - b1 * S1;
        const float* base = ring + buf * STG_FLOATS;
        const float4* e0 = reinterpret_cast<const float4*>(base);
        const float4* e1 = reinterpret_cast<const float4*>(base + H);

        if (s0 != 0 && s1 != 0) {
            // fast fused path (both CRF rows)
            float a0[NT] = {0.f, 0.f, 0.f, 0.f};
            float a1[NT] = {0.f, 0.f, 0.f, 0.f};
#pragma unroll
            for (int k = 0; k < 6; k++) {
                float4 x0 = e0[k * 32 + lane];
                float4 x1 = e1[k * 32 + lane];
#pragma unroll
                for (int t = 0; t < NT; t++) {
                    a0[t] += x0.x * wr[t][k].x + x0.y * wr[t][k].y +
                             x0.z * wr[t][k].z + x0.w * wr[t][k].w;
                    a1[t] += x1.x * wr[t][k].x + x1.y * wr[t][k].y +
                             x1.z * wr[t][k].z + x1.w * wr[t][k].w;
                }
            }
#pragma unroll
            for (int off = 16; off; off >>= 1)
#pragma unroll
                for (int t = 0; t < NT; t++) {
                    a0[t] += __shfl_xor_sync(0xFFFFFFFFu, a0[t], off);
                    a1[t] += __shfl_xor_sync(0xFFFFFFFFu, a1[t], off);
                }
            if (lane == 0) {
                reinterpret_cast<float4*>(g_feats)[b0 * S + (s0 - 1)] =
                    make_float4(a0[0] + cb0, a0[1] + cb1, a0[2] + cb2, a0[3] + cb3);
                reinterpret_cast<float4*>(g_feats)[b1 * S + (s1 - 1)] =
                    make_float4(a1[0] + cb0, a1[1] + cb1, a1[2] + cb2, a1[3] + cb3);
            }
        } else {
            // slow path: at least one cls row (64 of 32832 rows)
#pragma unroll
            for (int rr = 0; rr < 2; rr++) {
                const int bb = rr ? b1 : b0;
                const int ss = rr ? s1 : s0;
                const float4* e = rr ? e1 : e0;
                if (ss == 0) {
                    float l0 = 0.f, l1 = 0.f;
#pragma unroll
                    for (int k = 0; k < 6; k++) {
                        float4 x  = e[k * 32 + lane];
                        float4 w0 = __ldg(reinterpret_cast<const float4*>(fc2_W) + k * 32 + lane);
                        float4 w1 = __ldg(reinterpret_cast<const float4*>(fc2_W + H) + k * 32 + lane);
                        l0 += x.x * w0.x + x.y * w0.y + x.z * w0.z + x.w * w0.w;
                        l1 += x.x * w1.x + x.y * w1.y + x.z * w1.z + x.w * w1.w;
                    }
#pragma unroll
                    for (int off = 16; off; off >>= 1) {
                        l0 += __shfl_xor_sync(0xFFFFFFFFu, l0, off);
                        l1 += __shfl_xor_sync(0xFFFFFFFFu, l1, off);
                    }
                    if (lane == 0) {
                        g_logits[bb * 2 + 0] = l0 + __ldg(fc2_b + 0);
                        g_logits[bb * 2 + 1] = l1 + __ldg(fc2_b + 1);
                    }
                } else {
                    float acc[NT] = {0.f, 0.f, 0.f, 0.f};
#pragma unroll
                    for (int k = 0; k < 6; k++) {
                        float4 x = e[k * 32 + lane];
#pragma unroll
                        for (int t = 0; t < NT; t++)
                            acc[t] += x.x * wr[t][k].x + x.y * wr[t][k].y +
                                      x.z * wr[t][k].z + x.w * wr[t][k].w;
                    }
#pragma unroll
                    for (int off = 16; off; off >>= 1)
#pragma unroll
                        for (int t = 0; t < NT; t++)
                            acc[t] += __shfl_xor_sync(0xFFFFFFFFu, acc[t], off);
                    if (lane == 0) {
                        reinterpret_cast<float4*>(g_feats)[bb * S + (ss - 1)] =
                            make_float4(acc[0] + cb0, acc[1] + cb1,
                                        acc[2] + cb2, acc[3] + cb3);
                    }
                }
            }
        }
        __syncwarp();
        // Refill this buffer with the stage NBUF ahead.
        ISSUE_STAGE(it + NBUF * NW, ring + buf * STG_FLOATS);
        buf = (buf == NBUF - 1) ? 0 : buf + 1;
    }
#undef ISSUE_STAGE
}

// ---------------------------------------------------------------------------
// Kernel 2: per-batch CRF, SoA operator storage (conflict-free LDS).
//  Forward Z : binary tree over 255 M2 matrices (normalized + log accum)
//  Viterbi   : Hillis-Steele max-plus scan over 127 V4 ops, parallel
//              backtrace records, 127-step serial record chase.
// ---------------------------------------------------------------------------
__global__ void __launch_bounds__(256) k_crf(const int* __restrict__ labels,
                                             const int* __restrict__ isqa,
                                             const float* __restrict__ trans,
                                             float* __restrict__ out) {
    __shared__ __align__(16) float sf[S * NT];     // 8 KB feats (log)
    __shared__ float sA[16 * PSTR];                // 16 KB: M2 then V2 (SoA)
    __shared__ float sV4[16 * QSTR];               // 8 KB (SoA)
    __shared__ float sPa[16 * QSTR];               // 8 KB tree/scan buffer (SoA)
    __shared__ float slogs[QSTR];
    __shared__ float strn[16], sE[16];
    __shared__ int   sbpmid2[PSTR];
    __shared__ int   skmid4[QSTR];
    __shared__ unsigned int srec[QSTR];
    __shared__ unsigned char stag[S], spath[S];
    __shared__ float sZ;

    const int b   = blockIdx.x;
    const int tid = threadIdx.x;
    const float4* sf4 = reinterpret_cast<const float4*>(sf);

    // ---- P0: stage ----
    {
        const float4* fsrc = reinterpret_cast<const float4*>(g_feats + (size_t)b * S * NT);
        float4* f4 = reinterpret_cast<float4*>(sf);
        for (int i = tid; i < S; i += 256) f4[i] = fsrc[i];
        for (int i = tid; i < S; i += 256) {
            int tg = labels[b * S1 + 1 + i];
            stag[i] = (unsigned char)tg;
            out[OFF_TAGS + b * S + i] = (float)tg;
        }
        if (tid < 16) { float t = trans[tid]; strn[tid] = t; sE[tid] = __expf(t); }
    }
    __syncthreads();

    // ---- P1: M2 pair matrices (linear domain), one per thread, SoA store ----
    if (tid < NP) {
        const int p = tid;
        float4 f1 = sf4[2 * p + 1], f2 = sf4[2 * p + 2];
        float g[4] = {__expf(f1.x), __expf(f1.y), __expf(f1.z), __expf(f1.w)};
        float h[4] = {__expf(f2.x), __expf(f2.y), __expf(f2.z), __expf(f2.w)};
        float m[16];
#pragma unroll
        for (int i = 0; i < 4; i++) {
            float eg0 = sE[i * 4 + 0] * g[0], eg1 = sE[i * 4 + 1] * g[1];
            float eg2 = sE[i * 4 + 2] * g[2], eg3 = sE[i * 4 + 3] * g[3];
#pragma unroll
            for (int j = 0; j < 4; j++)
                m[i * 4 + j] = ((eg0 * sE[0 * 4 + j] + eg1 * sE[1 * 4 + j]) +
                                (eg2 * sE[2 * 4 + j] + eg3 * sE[3 * 4 + j])) * h[j];
        }
#pragma unroll
        for (int e = 0; e < 16; e++) sA[e * PSTR + p] = m[e];
    }
    __syncthreads();

    // ---- P2: forward Z via tree reduction over sPa (SoA) ----
    if (tid < 128) {
        float C[16];
        if (tid < 127) {
            float A[16], Bm[16];
#pragma unroll
            for (int e = 0; e < 16; e++) { A[e] = sA[e * PSTR + 2 * tid];
                                           Bm[e] = sA[e * PSTR + 2 * tid + 1]; }
            mm4(A, Bm, C);
        } else {
#pragma unroll
            for (int e = 0; e < 16; e++) C[e] = sA[e * PSTR + 254];
        }
        float ssum = 0.f;
#pragma unroll
        for (int e = 0; e < 16; e++) ssum += C[e];
        float inv = __fdividef(1.0f, ssum);
#pragma unroll
        for (int e = 0; e < 16; e++) sPa[e * QSTR + tid] = C[e] * inv;
        slogs[tid] = __logf(ssum);
    }
    __syncthreads();
#pragma unroll
    for (int n = 64; n >= 1; n >>= 1) {
        float C[16], lg = 0.f;
        if (tid < n) {
            float A[16], Bm[16];
#pragma unroll
            for (int e = 0; e < 16; e++) { A[e] = sPa[e * QSTR + 2 * tid];
                                           Bm[e] = sPa[e * QSTR + 2 * tid + 1]; }
            mm4(A, Bm, C);
            lg = slogs[2 * tid] + slogs[2 * tid + 1];
        }
        __syncthreads();
        if (tid < n) {
            float ssum = 0.f;
#pragma unroll
            for (int e = 0; e < 16; e++) ssum += C[e];
            float inv = __fdividef(1.0f, ssum);
#pragma unroll
            for (int e = 0; e < 16; e++) sPa[e * QSTR + tid] = C[e] * inv;
            slogs[tid] = lg + __logf(ssum);
        }
        __syncthreads();
    }
    if (tid == 0) {   // Z epilogue: alpha0 . Mtot, then step 511 + stop
        float4 f0 = sf4[0];
        float a[4] = {__expf(f0.x) * sE[8],  __expf(f0.y) * sE[9],
                      __expf(f0.z) * sE[10], __expf(f0.w) * sE[11]};
        float Mt[16];
#pragma unroll
        for (int e = 0; e < 16; e++) Mt[e] = sPa[e * QSTR + 0];
        float t[4];
#pragma unroll
        for (int j = 0; j < 4; j++)
            t[j] = (a[0] * Mt[0 * 4 + j] + a[1] * Mt[1 * 4 + j]) +
                   (a[2] * Mt[2 * 4 + j] + a[3] * Mt[3 * 4 + j]);
        float4 f511 = sf4[511];
        float ef[4] = {__expf(f511.x), __expf(f511.y), __expf(f511.z), __expf(f511.w)};
        float u[4];
#pragma unroll
        for (int j = 0; j < 4; j++)
            u[j] = ((t[0] * sE[0 * 4 + j] + t[1] * sE[1 * 4 + j]) +
                    (t[2] * sE[2 * 4 + j] + t[3] * sE[3 * 4 + j])) * ef[j];
        sZ = slogs[0] + __logf((u[0] * sE[3] + u[1] * sE[7]) +
                               (u[2] * sE[11] + u[3] * sE[15]));
    }
    __syncthreads();

    // ---- P3: V2 (max-plus) overwrites sA (SoA); mid-tag words ----
    if (tid < NP) {
        const int p = tid;
        float4 f1 = sf4[2 * p + 1], f2 = sf4[2 * p + 2];
        float f1a[4] = {f1.x, f1.y, f1.z, f1.w};
        float f2a[4] = {f2.x, f2.y, f2.z, f2.w};
        int word = 0;
#pragma unroll
        for (int i = 0; i < 4; i++) {
            float h0 = strn[i * 4 + 0] + f1a[0], h1 = strn[i * 4 + 1] + f1a[1];
            float h2 = strn[i * 4 + 2] + f1a[2], h3 = strn[i * 4 + 3] + f1a[3];
#pragma unroll
            for (int j = 0; j < 4; j++) {
                float mv;
                int k = argmax4(h0 + strn[0 * 4 + j], h1 + strn[1 * 4 + j],
                                h2 + strn[2 * 4 + j], h3 + strn[3 * 4 + j], mv);
                sA[(i * 4 + j) * PSTR + p] = mv + f2a[j];
                word |= k << (2 * (i * 4 + j));
            }
        }
        sbpmid2[p] = word;
    }
    __syncthreads();

    // ---- P4: V4 = V2 o V2 into sV4 and sPa (scan init); mid words ----
    if (tid < NQ) {
        float A[16], Bv[16];
#pragma unroll
        for (int e = 0; e < 16; e++) { A[e] = sA[e * PSTR + 2 * tid];
                                       Bv[e] = sA[e * PSTR + 2 * tid + 1]; }
        int word = 0;
#pragma unroll
        for (int i = 0; i < 4; i++)
#pragma unroll
            for (int j = 0; j < 4; j++) {
                float mv;
                int k = argmax4(A[i * 4 + 0] + Bv[0 * 4 + j], A[i * 4 + 1] + Bv[1 * 4 + j],
                                A[i * 4 + 2] + Bv[2 * 4 + j], A[i * 4 + 3] + Bv[3 * 4 + j], mv);
                sV4[(i * 4 + j) * QSTR + tid] = mv;
                sPa[(i * 4 + j) * QSTR + tid] = mv;
                word |= k << (2 * (i * 4 + j));
            }
        skmid4[tid] = word;
    }
    __syncthreads();

    // ---- P5: inclusive max-plus scan (Hillis-Steele, SoA) ----
#pragma unroll
    for (int d = 1; d < 128; d <<= 1) {
        float C[16];
        const bool act = (tid < NQ) && (tid >= d);
        if (act) {
            float A[16], Bm[16];
#pragma unroll
            for (int e = 0; e < 16; e++) { A[e] = sPa[e * QSTR + tid - d];
                                           Bm[e] = sPa[e * QSTR + tid]; }
            mp4(A, Bm, C);
        }
        __syncthreads();
        if (act) {
#pragma unroll
            for (int e = 0; e < 16; e++) sPa[e * QSTR + tid] = C[e];
        }
        __syncthreads();
    }

    // ---- P6: per-quad backtrace records (parallel) ----
    if (tid < NQ) {
        const int q = tid;
        float4 f0 = sf4[0];
        float d0v[4] = {f0.x + strn[8], f0.y + strn[9], f0.z + strn[10], f0.w + strn[11]};
        float de[4];
        if (q == 0) {
#pragma unroll
            for (int i = 0; i < 4; i++) de[i] = d0v[i];
        } else {
            float P[16];
#pragma unroll
            for (int e = 0; e < 16; e++) P[e] = sPa[e * QSTR + q - 1];
#pragma unroll
            for (int j = 0; j < 4; j++) {
                float mv;
                argmax4(d0v[0] + P[0 * 4 + j], d0v[1] + P[1 * 4 + j],
                        d0v[2] + P[2 * 4 + j], d0v[3] + P[3 * 4 + j], mv);
                de[j] = mv;
            }
        }
        float V[16];
#pragma unroll
        for (int e = 0; e < 16; e++) V[e] = sV4[e * QSTR + q];
        const int w4 = skmid4[q], w2a = sbpmid2[2 * q], w2b = sbpmid2[2 * q + 1];
        unsigned int rec = 0;
#pragma unroll
        for (int j = 0; j < 4; j++) {
            float mv;
            int i = argmax4(de[0] + V[0 * 4 + j], de[1] + V[1 * 4 + j],
                            de[2] + V[2 * 4 + j], de[3] + V[3 * 4 + j], mv);
            int k2 = (w4  >> (2 * ((i  << 2) | j)))  & 3;
            int m1 = (w2a >> (2 * ((i  << 2) | k2))) & 3;
            int m3 = (w2b >> (2 * ((k2 << 2) | j)))  & 3;
            rec |= (unsigned int)(i | (m1 << 2) | (k2 << 4) | (m3 << 6)) << (8 * j);
        }
        srec[q] = rec;
    }
    __syncthreads();

    // ---- P7: viterbi epilogue + serial record chase (tid 0) ----
    if (tid == 0) {
        float4 f0 = sf4[0];
        float d0v[4] = {f0.x + strn[8], f0.y + strn[9], f0.z + strn[10], f0.w + strn[11]};
        float P[16];
#pragma unroll
        for (int e = 0; e < 16; e++) P[e] = sPa[e * QSTR + 126];
        float e[4];
#pragma unroll
        for (int j = 0; j < 4; j++) {
            float mv;
            argmax4(d0v[0] + P[0 * 4 + j], d0v[1] + P[1 * 4 + j],
                    d0v[2] + P[2 * 4 + j], d0v[3] + P[3 * 4 + j], mv);
            e[j] = mv;
        }
        float Vl[16];
#pragma unroll
        for (int k = 0; k < 16; k++) Vl[k] = sA[k * PSTR + 254];
        float g0 = fmaxf(fmaxf(e[0] + Vl[0], e[1] + Vl[4]), fmaxf(e[2] + Vl[8],  e[3] + Vl[12]));
        float g1 = fmaxf(fmaxf(e[0] + Vl[1], e[1] + Vl[5]), fmaxf(e[2] + Vl[9],  e[3] + Vl[13]));
        float g2 = fmaxf(fmaxf(e[0] + Vl[2], e[1] + Vl[6]), fmaxf(e[2] + Vl[10], e[3] + Vl[14]));
        float g3 = fmaxf(fmaxf(e[0] + Vl[3], e[1] + Vl[7]), fmaxf(e[2] + Vl[11], e[3] + Vl[15]));
        float4 f511 = sf4[511];
        float h0 = fmaxf(fmaxf(g0 + strn[0], g1 + strn[4]), fmaxf(g2 + strn[8],  g3 + strn[12])) + f511.x;
        float h1 = fmaxf(fmaxf(g0 + strn[1], g1 + strn[5]), fmaxf(g2 + strn[9],  g3 + strn[13])) + f511.y;
        float h2 = fmaxf(fmaxf(g0 + strn[2], g1 + strn[6]), fmaxf(g2 + strn[10], g3 + strn[14])) + f511.z;
        float h3 = fmaxf(fmaxf(g0 + strn[3], g1 + strn[7]), fmaxf(g2 + strn[11], g3 + strn[15])) + f511.w;
        float mv;
        int lt = argmax4(h0 + strn[3], h1 + strn[7], h2 + strn[11], h3 + strn[15], mv);
        spath[511] = (unsigned char)lt;
        int t510 = argmax4(g0 + strn[0 * 4 + lt], g1 + strn[1 * 4 + lt],
                           g2 + strn[2 * 4 + lt], g3 + strn[3 * 4 + lt], mv);
        spath[510] = (unsigned char)t510;
        int j = t510;
        int i508 = argmax4(e[0] + Vl[0 * 4 + j], e[1] + Vl[1 * 4 + j],
                           e[2] + Vl[2 * 4 + j], e[3] + Vl[3 * 4 + j], mv);
        int mid = (sbpmid2[254] >> (2 * ((i508 << 2) | j))) & 3;
        spath[509] = (unsigned char)mid;
        spath[508] = (unsigned char)i508;
        j = i508;
        unsigned int* path32 = reinterpret_cast<unsigned int*>(spath);
#pragma unroll 4
        for (int q = NQ - 1; q >= 0; q--) {
            unsigned int w = srec[q];
            unsigned int r = (w >> (8 * j)) & 255u;
            path32[q] = (r & 3u) | (((r >> 2) & 3u) << 8) |
                        (((r >> 4) & 3u) << 16) | (((r >> 6) & 3u) << 24);
            j = (int)(r & 3u);
        }
    }
    __syncthreads();

    // ---- P8: gold score (warp 0), isqa (tid 32), path writeback (all) ----
    const int warp = tid >> 5, lane = tid & 31;
    if (warp == 0) {
        float em = 0.f, tr = 0.f;
        for (int s = lane; s < S; s += 32)     em += sf[s * NT + stag[s]];
        for (int s = lane; s < S - 1; s += 32) tr += strn[stag[s] * NT + stag[s + 1]];
        float v = em + tr;
#pragma unroll
        for (int off = 16; off; off >>= 1) v += __shfl_xor_sync(0xFFFFFFFFu, v, off);
        if (lane == 0) {
            float gold = v + strn[8 + stag[0]] + strn[stag[S - 1] * 4 + 3];
            g_dloss[b] = sZ - gold;
        }
    } else if (tid == 32) {
        float l0 = g_logits[b * 2], l1 = g_logits[b * 2 + 1];
        float mm  = fmaxf(l0, l1);
        float lse = mm + __logf(__expf(l0 - mm) + __expf(l1 - mm));
        int y = isqa[b];
        g_iloss[b] = -((y ? l1 : l0) - lse);
        out[OFF_IPRED + b] = (l1 > l0) ? 1.0f : 0.0f;
        out[OFF_ISQA + b] = (float)y;
    }
    for (int i = tid; i < S; i += 256)
        out[OFF_CPRED + b * S + i] = (float)spath[i];
}

// ---------------------------------------------------------------------------
// Kernel 3: reduce per-batch losses
// ---------------------------------------------------------------------------
__global__ void k_final(float* __restrict__ out) {
    const int tid = threadIdx.x;   // 64 threads
    float d  = g_dloss[tid];
    float il = g_iloss[tid];
#pragma unroll
    for (int off = 16; off; off >>= 1) {
        d  += __shfl_xor_sync(0xFFFFFFFFu, d, off);
        il += __shfl_xor_sync(0xFFFFFFFFu, il, off);
    }
    __shared__ float sd2[2], si2[2];
    if ((tid & 31) == 0) { sd2[tid >> 5] = d; si2[tid >> 5] = il; }
    __syncthreads();
    if (tid == 0) {
        out[OFF_CLOSS] = (sd2[0] + sd2[1]) * (1.0f / 64.0f);
        out[OFF_ILOSS] = (si2[0] + si2[1]) * (1.0f / 64.0f);
    }
}

// ---------------------------------------------------------------------------
extern "C" void kernel_launch(void* const* d_in, const int* in_sizes, int n_in,
                              void* d_out, int out_size) {
    const float* emb    = (const float*)d_in[0];
    const int*   labels = (const int*)d_in[1];
    const int*   isqa   = (const int*)d_in[2];
    const float* fc2_W  = (const float*)d_in[3];
    const float* fc2_b  = (const float*)d_in[4];
    const float* crf_W  = (const float*)d_in[5];
    const float* crf_b  = (const float*)d_in[6];
    const float* trans  = (const float*)d_in[7];
    float* out = (float*)d_out;

    cudaFuncSetAttribute(k_feats, cudaFuncAttributeMaxDynamicSharedMemorySize,
                         SMEM_BYTES);
    k_feats<<<444, 128, SMEM_BYTES>>>(emb, fc2_W, fc2_b, crf_W, crf_b);
    k_crf<<<B, 256>>>(labels, isqa, trans, out);
    k_final<<<1, 64>>>(out);
}